// round 14
// baseline (speedup 1.0000x reference)
#include <cuda_runtime.h>
#include <cuda_bf16.h>
#include <math.h>

// Problem constants
#define Bc   64
#define Lc   2048
#define Dc   128
#define Hc   4
#define Ac   128
#define Mc   16
#define Vc   100000
#define NNZc 262144
#define HDc  32
#define GAMMAc 0.3
#define BETAc  1.0

#define K1BLK 148
#define K3BLK 20

typedef unsigned long long ull;

#define FMA2(acc, a, b) asm("fma.rn.f32x2 %0, %1, %2, %0;" : "+l"(acc) : "l"(a), "l"(b))
__device__ __forceinline__ ull pack2(float x, float y) {
    ull d; asm("mov.b64 %0, {%1, %2};" : "=l"(d) : "f"(x), "f"(y)); return d;
}
__device__ __forceinline__ float2 unpack2(ull v) {
    float2 r; asm("mov.b64 {%0, %1}, %2;" : "=f"(r.x), "=f"(r.y) : "l"(v)); return r;
}

// ---------------- scratch (static __device__, no allocation) ----------------
__device__ __align__(16) float  g_sigT[(size_t)Vc * Mc];
__device__ __align__(16) float  g_PhiP_part[K1BLK * Mc * Ac];  // [blk][m][a]
__device__ double g_sizeP_part[K1BLK * Mc];                    // [blk][m]
__device__ __align__(16) float  g_PhiQ[Bc * Ac];
__device__ double g_psum[Bc * Mc];
__device__ __align__(16) float  g_AQ[Bc * Ac];
__device__ __align__(16) float  g_BP[Mc * Ac];
__device__ __align__(16) float  g_Vp[Mc * HDc];
__device__ __align__(16) float  g_Z[Bc * HDc];
__device__ __align__(16) float  g_C[Bc * Dc * Hc];   // [b][d][h]

// ---------------- grid barrier (sense-reversal via monotonic epoch) ----------------
__device__ volatile unsigned g_barCnt;
__device__ volatile unsigned g_epoch;

__device__ __forceinline__ void grid_barrier(unsigned nblk) {
    __syncthreads();
    if (threadIdx.x == 0) {
        unsigned e = g_epoch;
        __threadfence();
        unsigned old = atomicAdd((unsigned*)&g_barCnt, 1u);
        if (old == nblk - 1) {
            g_barCnt = 0;
            __threadfence();
            atomicAdd((unsigned*)&g_epoch, 1u);
        } else {
            while (g_epoch == e) { __nanosleep(64); }
        }
        __threadfence();
    }
    __syncthreads();
}

// ---------------- K1: vocab pass + zero PhiQ/psum, partial PhiP/sizeP ----------------
#define SSTR 18
__global__ void __launch_bounds__(512) k1_vocab(const float* __restrict__ phi_logits,
                                                const float* __restrict__ atom_emb) {
    __shared__ __align__(16) float sS[2][32 * SSTR];
    __shared__ __align__(16) float sRed[16 * 128];

    const int t = threadIdx.x;
    const int bid = blockIdx.x;
    const int w = t >> 5, lane = t & 31;
    const int mS = t >> 5, vS = t & 31;

    // zero accumulators consumed by k2 (k1 completes before k2 launches)
    {
        int idx = bid * 512 + t;
        if (idx < Bc * Ac) g_PhiQ[idx] = 0.f;
        if (idx < Bc * Mc) g_psum[idx] = 0.0;
    }

    ull acc2[8][4];
#pragma unroll
    for (int mp = 0; mp < 8; mp++)
#pragma unroll
        for (int c = 0; c < 4; c++) acc2[mp][c] = pack2(0.f, 0.f);
    double szAcc = 0.0;

    const int nTiles = Vc / 32;   // 3125
    int gt = bid;

    {
        float x = phi_logits[(size_t)mS * Vc + gt * 32 + vS];
        float s = 1.0f / (1.0f + __expf(-x));
        sS[0][vS * SSTR + mS] = s;
        szAcc += (double)s;
    }
    float4 eA = *reinterpret_cast<const float4*>(&atom_emb[((size_t)gt * 32 + w) * Ac + lane * 4]);
    float4 eB = *reinterpret_cast<const float4*>(&atom_emb[((size_t)gt * 32 + w + 16) * Ac + lane * 4]);
    __syncthreads();

    int cur = 0;
    for (; gt < nTiles; gt += K1BLK) {
        const int gtn = gt + K1BLK;
        const bool has = gtn < nTiles;
        float xn = 0.f; float4 eAn, eBn;
        if (has) {
            xn  = phi_logits[(size_t)mS * Vc + gtn * 32 + vS];
            eAn = *reinterpret_cast<const float4*>(&atom_emb[((size_t)gtn * 32 + w) * Ac + lane * 4]);
            eBn = *reinterpret_cast<const float4*>(&atom_emb[((size_t)gtn * 32 + w + 16) * Ac + lane * 4]);
        }
        {
            int v2 = t >> 4, m2 = t & 15;
            g_sigT[((size_t)gt * 32 + v2) * 16 + m2] = sS[cur][v2 * SSTR + m2];
        }
        {
            ull eDA[4], eDB[4];
            eDA[0] = pack2(eA.x, eA.x); eDA[1] = pack2(eA.y, eA.y);
            eDA[2] = pack2(eA.z, eA.z); eDA[3] = pack2(eA.w, eA.w);
            eDB[0] = pack2(eB.x, eB.x); eDB[1] = pack2(eB.y, eB.y);
            eDB[2] = pack2(eB.z, eB.z); eDB[3] = pack2(eB.w, eB.w);
            const ull* spA = reinterpret_cast<const ull*>(&sS[cur][w * SSTR]);
            const ull* spB = reinterpret_cast<const ull*>(&sS[cur][(w + 16) * SSTR]);
#pragma unroll
            for (int mp = 0; mp < 8; mp++) {
                ull sA2 = spA[mp];
                ull sB2 = spB[mp];
#pragma unroll
                for (int c = 0; c < 4; c++) {
                    FMA2(acc2[mp][c], sA2, eDA[c]);
                    FMA2(acc2[mp][c], sB2, eDB[c]);
                }
            }
        }
        if (has) {
            float s = 1.0f / (1.0f + __expf(-xn));
            sS[cur ^ 1][vS * SSTR + mS] = s;
            szAcc += (double)s;
        }
        __syncthreads();
        eA = eAn; eB = eBn; cur ^= 1;
    }

    // sizeP partial
    {
        double s = szAcc;
#pragma unroll
        for (int k = 16; k; k >>= 1) s += __shfl_xor_sync(0xffffffffu, s, k);
        if (lane == 0) g_sizeP_part[bid * 16 + w] = s;
    }
    // PhiP partial
    for (int m = 0; m < 16; m++) {
        const int mp = m >> 1, hi = m & 1;
        __syncthreads();
        float4 v;
        float2 u0 = unpack2(acc2[mp][0]);
        float2 u1 = unpack2(acc2[mp][1]);
        float2 u2 = unpack2(acc2[mp][2]);
        float2 u3 = unpack2(acc2[mp][3]);
        v.x = hi ? u0.y : u0.x; v.y = hi ? u1.y : u1.x;
        v.z = hi ? u2.y : u2.x; v.w = hi ? u3.y : u3.x;
        *reinterpret_cast<float4*>(&sRed[w * 128 + lane * 4]) = v;
        __syncthreads();
        if (t < 128) {
            float s = 0.f;
#pragma unroll
            for (int w2 = 0; w2 < 16; w2++) s += sRed[w2 * 128 + t];
            g_PhiP_part[(bid * 16 + m) * 128 + t] = s;
        }
    }
}

// ---------------- K2: nnz gather ----------------
#define K2_CHUNK 128
__global__ void __launch_bounds__(128) k2_nnz(const int* __restrict__ qids,
                                              const int* __restrict__ qoffs,
                                              const float* __restrict__ atom_emb) {
    __shared__ int sOffs[Bc + 1];
    __shared__ int sIds[K2_CHUNK];
    const int t = threadIdx.x;
    if (t < Bc + 1) sOffs[t] = qoffs[t];
    const int i0 = blockIdx.x * K2_CHUNK;
    sIds[t] = qids[i0 + t];
    __syncthreads();

    int lo = 0, hi = Bc - 1;
    while (lo < hi) { int mid = (lo + hi) >> 1; if (sOffs[mid + 1] <= i0) lo = mid + 1; else hi = mid; }
    int seg = lo;
    int nxt = sOffs[seg + 1];

    float accQ = 0.f;
    double accP = 0.0;
    bool dirty = false;
    const int iend = i0 + K2_CHUNK;
    int i = i0;
    while (i < iend) {
        if (i >= nxt) {
            if (dirty) {
                atomicAdd(&g_PhiQ[seg * Ac + t], accQ);
                if (t < 16) atomicAdd(&g_psum[seg * 16 + t], accP);
                accQ = 0.f; accP = 0.0; dirty = false;
            }
            do { seg++; nxt = sOffs[seg + 1]; } while (i >= nxt);
        }
        int lim = nxt < iend ? nxt : iend;
        int cnt = lim - i;
        int base = i - i0;
        dirty = true;
        int k = 0;
        for (; k + 8 <= cnt; k += 8) {
            int id[8];
#pragma unroll
            for (int j = 0; j < 8; j++) id[j] = sIds[base + k + j];
            float a[8];
#pragma unroll
            for (int j = 0; j < 8; j++) a[j] = atom_emb[(size_t)id[j] * Ac + t];
            accQ += ((a[0] + a[1]) + (a[2] + a[3])) + ((a[4] + a[5]) + (a[6] + a[7]));
            if (t < 16) {
                double s = 0.0;
#pragma unroll
                for (int j = 0; j < 8; j++) s += (double)g_sigT[(size_t)id[j] * 16 + t];
                accP += s;
            }
        }
        for (; k < cnt; k++) {
            int id = sIds[base + k];
            accQ += atom_emb[(size_t)id * Ac + t];
            if (t < 16) accP += (double)g_sigT[(size_t)id * 16 + t];
        }
        i = lim;
    }
    if (dirty) {
        atomicAdd(&g_PhiQ[seg * Ac + t], accQ);
        if (t < 16) atomicAdd(&g_psum[seg * 16 + t], accP);
    }
}

// ---------------- K3: fused epilogue, 20 blocks x 512, grid barriers ----------------
__global__ void __launch_bounds__(512) k3(const int*   __restrict__ qoffs,
                                          const float* __restrict__ W_A,
                                          const float* __restrict__ W_B,
                                          const float* __restrict__ W_val,
                                          const float* __restrict__ b_val,
                                          const float* __restrict__ W_out,
                                          const float* __restrict__ size_w) {
    __shared__ __align__(16) float sv[4][Ac];
    __shared__ double sSz[Mc];
    __shared__ float sAttn[Bc * Mc];
    const int t = threadIdx.x;
    const int bid = blockIdx.x;
    const int g = t >> 7, l = t & 127;
    const int u = (bid << 2) | g;          // 80 units

    // ---- Part A: stage vector ----
    {
        float val;
        if (u < Bc) {
            val = g_PhiQ[u * Ac + l];
        } else {
            const int m = u - Bc;
            float s = 0.f;
#pragma unroll 8
            for (int blk = 0; blk < K1BLK; blk++) s += g_PhiP_part[(blk * 16 + m) * 128 + l];
            val = s;
        }
        sv[g][l] = val;
    }
    __syncthreads();
    // ---- Part A: dots ----
    if (u < Bc) {
        const float* svg = sv[g];
        float acc = 0.f;
        const float* wr = &W_A[l * Ac];
#pragma unroll 16
        for (int a = 0; a < Ac; a += 4) {
            float4 w4 = *reinterpret_cast<const float4*>(&wr[a]);
            acc += w4.x * svg[a] + w4.y * svg[a + 1] + w4.z * svg[a + 2] + w4.w * svg[a + 3];
        }
        g_AQ[u * Ac + l] = acc;
    } else {
        const int m = u - Bc;
        const float* svg = sv[g];
        float acc = 0.f;
        const float* wr = &W_B[l * Ac];
#pragma unroll 16
        for (int a = 0; a < Ac; a += 4) {
            float4 w4 = *reinterpret_cast<const float4*>(&wr[a]);
            acc += w4.x * svg[a] + w4.y * svg[a + 1] + w4.z * svg[a + 2] + w4.w * svg[a + 3];
        }
        g_BP[m * Ac + l] = acc;
        if (l < HDc) {
            float a2 = 0.f;
            const float* wv = &W_val[l * Ac];
#pragma unroll 16
            for (int a = 0; a < Ac; a++) a2 += wv[a] * svg[a];
            g_Vp[m * HDc + l] = a2 + b_val[l];
        }
    }
    // block 0: sizeP reduction
    if (bid == 0 && t < 64) {
        const int m = t >> 2, q = t & 3;
        double s = 0.0;
        for (int blk = q; blk < K1BLK; blk += 4) s += g_sizeP_part[blk * 16 + m];
        s += __shfl_xor_sync(0xffffffffu, s, 1);
        s += __shfl_xor_sync(0xffffffffu, s, 2);
        if (q == 0) sSz[m] = s;
    }

    grid_barrier(K3BLK);

    // ---- Part B (block 0 only): fp64 scores -> softmax -> Z ----
    if (bid == 0) {
#pragma unroll
        for (int rep = 0; rep < 2; rep++) {
            const int t2 = rep * 512 + t;
            const int b = t2 >> 4, m = t2 & 15;
            float dotv = 0.f;
            const float4* aq = reinterpret_cast<const float4*>(&g_AQ[b * Ac]);
            const float4* bp = reinterpret_cast<const float4*>(&g_BP[m * Ac]);
#pragma unroll 8
            for (int i = 0; i < Ac / 4; i++) {
                float4 a4 = aq[i], b4 = bp[i];
                dotv += a4.x * b4.x + a4.y * b4.y + a4.z * b4.z + a4.w * b4.w;
            }
            double szQ = (double)(qoffs[b + 1] - qoffs[b]);
            double szP = sSz[m];
            double delta = szQ + szP - 2.0 * g_psum[b * 16 + m];
            double score = -GAMMAc * delta + BETAc * (double)dotv
                         + (double)size_w[0] * szQ + (double)size_w[1] * szP;
            double mx = score;
#pragma unroll
            for (int k = 8; k; k >>= 1) mx = fmax(mx, __shfl_xor_sync(0xffffffffu, mx, k));
            double e = exp(score - mx);
            double ssum = e;
#pragma unroll
            for (int k = 8; k; k >>= 1) ssum += __shfl_xor_sync(0xffffffffu, ssum, k);
            sAttn[t2] = (float)(e / ssum);
        }
        __syncthreads();
        for (int o = t; o < Bc * HDc; o += 512) {
            int bb = o >> 5, hd = o & 31;
            float z = 0.f;
#pragma unroll
            for (int mm = 0; mm < 16; mm++) z += sAttn[bb * 16 + mm] * g_Vp[mm * HDc + hd];
            g_Z[o] = z;
        }
    }

    grid_barrier(K3BLK);

    // ---- Part C (64 units): C[b][d][h] ----
    if (u < Bc) {
        const int b = u, d = l;
        float zl[HDc];
        const float4* zp = reinterpret_cast<const float4*>(&g_Z[b * HDc]);
#pragma unroll
        for (int j = 0; j < HDc / 4; j++) {
            float4 z4 = zp[j];
            zl[j * 4 + 0] = z4.x; zl[j * 4 + 1] = z4.y; zl[j * 4 + 2] = z4.z; zl[j * 4 + 3] = z4.w;
        }
        const float4* wr = reinterpret_cast<const float4*>(&W_out[d * Dc]);
        float4 acc = make_float4(0.f, 0.f, 0.f, 0.f);
#pragma unroll
        for (int j4 = 0; j4 < 8; j4++) {
            float4 w0 = wr[j4];
            float4 w1 = wr[8 + j4];
            float4 w2 = wr[16 + j4];
            float4 w3 = wr[24 + j4];
            float z0 = zl[j4 * 4], z1 = zl[j4 * 4 + 1], z2 = zl[j4 * 4 + 2], z3 = zl[j4 * 4 + 3];
            acc.x += w0.x * z0 + w0.y * z1 + w0.z * z2 + w0.w * z3;
            acc.y += w1.x * z0 + w1.y * z1 + w1.z * z2 + w1.w * z3;
            acc.z += w2.x * z0 + w2.y * z1 + w2.z * z2 + w2.w * z3;
            acc.w += w3.x * z0 + w3.y * z1 + w3.z * z2 + w3.w * z3;
        }
        *reinterpret_cast<float4*>(&g_C[(b * Dc + d) * Hc]) = acc;
    }
}

// ---------------- K5: token pass — 9-shfl critical path, local softmax ----------------
// After the 6-shfl reduction each lane owns head h=lane&3's logit. 3x shfl_xor
// fetches the other three logits; exp + normalization happen locally (no max
// subtract: logits ~ N(0,1)). The head permutation (h, h^1, h^2, h^3) is folded
// into a one-time XOR swizzle of the c registers.
__global__ void __launch_bounds__(256) k5_tokens(const float* __restrict__ ts,
                                                 const float* __restrict__ W_gate,
                                                 const float* __restrict__ b_gate,
                                                 const float* __restrict__ b_out,
                                                 float* __restrict__ out) {
    const int t = threadIdx.x, w = t >> 5, lane = t & 31;
    const int b = blockIdx.x >> 4, part = blockIdx.x & 15;
    const bool odd1 = lane & 1, odd2 = lane & 2;

    float4 wg[4];
#pragma unroll
    for (int h = 0; h < 4; h++) wg[h] = *reinterpret_cast<const float4*>(&W_gate[h * Dc + lane * 4]);
    const float bg = b_gate[lane & 3];
    const float4 bo = *reinterpret_cast<const float4*>(&b_out[lane * 4]);
    float4 c[4];
#pragma unroll
    for (int j = 0; j < 4; j++) {
        float4 v = *reinterpret_cast<const float4*>(&g_C[(b * Dc + lane * 4 + j) * Hc]);
        // swizzle components into head order (h, h^1, h^2, h^3)
        if (odd1) v = make_float4(v.y, v.x, v.w, v.z);
        if (odd2) v = make_float4(v.z, v.w, v.x, v.y);
        c[j] = v;
    }

    const float* xb = ts + (size_t)b * Lc * Dc;
    float* ob = out + (size_t)b * Lc * Dc;
    const int l0 = part * 128 + w * 16;
#pragma unroll 2
    for (int k = 0; k < 16; k++) {
        const int l = l0 + k;
        const float4 x = *reinterpret_cast<const float4*>(&xb[l * Dc + lane * 4]);
        float p0 = x.x * wg[0].x + x.y * wg[0].y + x.z * wg[0].z + x.w * wg[0].w;
        float p1 = x.x * wg[1].x + x.y * wg[1].y + x.z * wg[1].z + x.w * wg[1].w;
        float p2 = x.x * wg[2].x + x.y * wg[2].y + x.z * wg[2].z + x.w * wg[2].w;
        float p3 = x.x * wg[3].x + x.y * wg[3].y + x.z * wg[3].z + x.w * wg[3].w;
        // merge 4 head-partials -> lane owns head (lane&3): 3 shfl
        float q = odd1 ? p1 : p0, r = odd1 ? p0 : p1;
        q += __shfl_xor_sync(0xffffffffu, r, 1);
        float s2 = odd1 ? p3 : p2, u = odd1 ? p2 : p3;
        s2 += __shfl_xor_sync(0xffffffffu, u, 1);
        float v = odd2 ? s2 : q, wm = odd2 ? q : s2;
        v += __shfl_xor_sync(0xffffffffu, wm, 2);
        // finish across nibbles: 3 shfl
        v += __shfl_xor_sync(0xffffffffu, v, 4);
        v += __shfl_xor_sync(0xffffffffu, v, 8);
        v += __shfl_xor_sync(0xffffffffu, v, 16);
        // own logit + fetch the other three: 3 shfl
        float pA = v + bg;
        float pB = __shfl_xor_sync(0xffffffffu, pA, 1);
        float pC = __shfl_xor_sync(0xffffffffu, pA, 2);
        float pD = __shfl_xor_sync(0xffffffffu, pA, 3);
        // local softmax (no max subtract; logits ~ N(0,1))
        float e0 = __expf(pA), e1 = __expf(pB), e2 = __expf(pC), e3 = __expf(pD);
        float inv = __fdividef(1.f, (e0 + e1) + (e2 + e3));
        float4 o;
        o.x = bo.x + (e0 * c[0].x + e1 * c[0].y + e2 * c[0].z + e3 * c[0].w) * inv;
        o.y = bo.y + (e0 * c[1].x + e1 * c[1].y + e2 * c[1].z + e3 * c[1].w) * inv;
        o.z = bo.z + (e0 * c[2].x + e1 * c[2].y + e2 * c[2].z + e3 * c[2].w) * inv;
        o.w = bo.w + (e0 * c[3].x + e1 * c[3].y + e2 * c[3].z + e3 * c[3].w) * inv;
        *reinterpret_cast<float4*>(&ob[l * Dc + lane * 4]) = o;
    }
}

// ---------------- launcher ----------------
extern "C" void kernel_launch(void* const* d_in, const int* in_sizes, int n_in,
                              void* d_out, int out_size) {
    const float* token_states = (const float*)d_in[0];
    const int*   query_ids    = (const int*)d_in[1];
    const int*   query_offs   = (const int*)d_in[2];
    const float* atom_emb     = (const float*)d_in[3];
    const float* phi_logits   = (const float*)d_in[4];
    const float* W_A          = (const float*)d_in[5];
    const float* W_B          = (const float*)d_in[6];
    const float* W_val        = (const float*)d_in[7];
    const float* b_val        = (const float*)d_in[8];
    const float* W_gate       = (const float*)d_in[9];
    const float* b_gate       = (const float*)d_in[10];
    const float* W_out        = (const float*)d_in[11];
    const float* b_out        = (const float*)d_in[12];
    const float* size_w       = (const float*)d_in[13];
    float* out = (float*)d_out;

    k1_vocab<<<K1BLK, 512>>>(phi_logits, atom_emb);
    k2_nnz<<<NNZc / K2_CHUNK, 128>>>(query_ids, query_offs, atom_emb);
    k3<<<K3BLK, 512>>>(query_offs, W_A, W_B, W_val, b_val, W_out, size_w);
    k5_tokens<<<Bc * 16, 256>>>(token_states, W_gate, b_gate, b_out, out);
}

// round 15
// speedup vs baseline: 1.3808x; 1.3808x over previous
#include <cuda_runtime.h>
#include <cuda_bf16.h>
#include <math.h>

// Problem constants
#define Bc   64
#define Lc   2048
#define Dc   128
#define Hc   4
#define Ac   128
#define Mc   16
#define Vc   100000
#define NNZc 262144
#define HDc  32
#define GAMMAc 0.3
#define BETAc  1.0

#define K1BLK 148
#define K45BLK 148

typedef unsigned long long ull;

#define FMA2(acc, a, b) asm("fma.rn.f32x2 %0, %1, %2, %0;" : "+l"(acc) : "l"(a), "l"(b))
__device__ __forceinline__ ull pack2(float x, float y) {
    ull d; asm("mov.b64 %0, {%1, %2};" : "=l"(d) : "f"(x), "f"(y)); return d;
}
__device__ __forceinline__ float2 unpack2(ull v) {
    float2 r; asm("mov.b64 {%0, %1}, %2;" : "=f"(r.x), "=f"(r.y) : "l"(v)); return r;
}

// ---------------- scratch (static __device__, no allocation) ----------------
__device__ __align__(16) float  g_sigT[(size_t)Vc * Mc];
__device__ __align__(16) float  g_PhiP_part[K1BLK * Mc * Ac];  // [blk][m][a]
__device__ double g_sizeP_part[K1BLK * Mc];                    // [blk][m]
__device__ __align__(16) float  g_PhiQ[Bc * Ac];
__device__ double g_psum[Bc * Mc];
__device__ __align__(16) float  g_AQ[Bc * Ac];
__device__ __align__(16) float  g_BP[Mc * Ac];
__device__ __align__(16) float  g_Vp[Mc * HDc];
__device__ __align__(16) float  g_Z[Bc * HDc];
__device__ __align__(16) float  g_C[Bc * Dc * Hc];   // [b][d][h]

// ---------------- grid barrier (sense-reversal via monotonic epoch) ----------------
__device__ volatile unsigned g_barCnt;
__device__ volatile unsigned g_epoch;

__device__ __forceinline__ void grid_barrier(unsigned nblk) {
    __syncthreads();
    if (threadIdx.x == 0) {
        unsigned e = g_epoch;
        __threadfence();
        unsigned old = atomicAdd((unsigned*)&g_barCnt, 1u);
        if (old == nblk - 1) {
            g_barCnt = 0;
            __threadfence();
            atomicAdd((unsigned*)&g_epoch, 1u);
        } else {
            while (g_epoch == e) { __nanosleep(64); }
        }
        __threadfence();
    }
    __syncthreads();
}

// ---------------- K1: vocab pass + zero PhiQ/psum, partial PhiP/sizeP ----------------
#define SSTR 18
__global__ void __launch_bounds__(512) k1_vocab(const float* __restrict__ phi_logits,
                                                const float* __restrict__ atom_emb) {
    __shared__ __align__(16) float sS[2][32 * SSTR];
    __shared__ __align__(16) float sRed[16 * 128];

    const int t = threadIdx.x;
    const int bid = blockIdx.x;
    const int w = t >> 5, lane = t & 31;
    const int mS = t >> 5, vS = t & 31;

    // zero accumulators consumed by k2 (k1 completes before k2 launches)
    {
        int idx = bid * 512 + t;
        if (idx < Bc * Ac) g_PhiQ[idx] = 0.f;
        if (idx < Bc * Mc) g_psum[idx] = 0.0;
    }

    ull acc2[8][4];
#pragma unroll
    for (int mp = 0; mp < 8; mp++)
#pragma unroll
        for (int c = 0; c < 4; c++) acc2[mp][c] = pack2(0.f, 0.f);
    double szAcc = 0.0;

    const int nTiles = Vc / 32;   // 3125
    int gt = bid;

    {
        float x = phi_logits[(size_t)mS * Vc + gt * 32 + vS];
        float s = 1.0f / (1.0f + __expf(-x));
        sS[0][vS * SSTR + mS] = s;
        szAcc += (double)s;
    }
    float4 eA = *reinterpret_cast<const float4*>(&atom_emb[((size_t)gt * 32 + w) * Ac + lane * 4]);
    float4 eB = *reinterpret_cast<const float4*>(&atom_emb[((size_t)gt * 32 + w + 16) * Ac + lane * 4]);
    __syncthreads();

    int cur = 0;
    for (; gt < nTiles; gt += K1BLK) {
        const int gtn = gt + K1BLK;
        const bool has = gtn < nTiles;
        float xn = 0.f; float4 eAn, eBn;
        if (has) {
            xn  = phi_logits[(size_t)mS * Vc + gtn * 32 + vS];
            eAn = *reinterpret_cast<const float4*>(&atom_emb[((size_t)gtn * 32 + w) * Ac + lane * 4]);
            eBn = *reinterpret_cast<const float4*>(&atom_emb[((size_t)gtn * 32 + w + 16) * Ac + lane * 4]);
        }
        {
            int v2 = t >> 4, m2 = t & 15;
            g_sigT[((size_t)gt * 32 + v2) * 16 + m2] = sS[cur][v2 * SSTR + m2];
        }
        {
            ull eDA[4], eDB[4];
            eDA[0] = pack2(eA.x, eA.x); eDA[1] = pack2(eA.y, eA.y);
            eDA[2] = pack2(eA.z, eA.z); eDA[3] = pack2(eA.w, eA.w);
            eDB[0] = pack2(eB.x, eB.x); eDB[1] = pack2(eB.y, eB.y);
            eDB[2] = pack2(eB.z, eB.z); eDB[3] = pack2(eB.w, eB.w);
            const ull* spA = reinterpret_cast<const ull*>(&sS[cur][w * SSTR]);
            const ull* spB = reinterpret_cast<const ull*>(&sS[cur][(w + 16) * SSTR]);
#pragma unroll
            for (int mp = 0; mp < 8; mp++) {
                ull sA2 = spA[mp];
                ull sB2 = spB[mp];
#pragma unroll
                for (int c = 0; c < 4; c++) {
                    FMA2(acc2[mp][c], sA2, eDA[c]);
                    FMA2(acc2[mp][c], sB2, eDB[c]);
                }
            }
        }
        if (has) {
            float s = 1.0f / (1.0f + __expf(-xn));
            sS[cur ^ 1][vS * SSTR + mS] = s;
            szAcc += (double)s;
        }
        __syncthreads();
        eA = eAn; eB = eBn; cur ^= 1;
    }

    // sizeP partial
    {
        double s = szAcc;
#pragma unroll
        for (int k = 16; k; k >>= 1) s += __shfl_xor_sync(0xffffffffu, s, k);
        if (lane == 0) g_sizeP_part[bid * 16 + w] = s;
    }
    // PhiP partial
    for (int m = 0; m < 16; m++) {
        const int mp = m >> 1, hi = m & 1;
        __syncthreads();
        float4 v;
        float2 u0 = unpack2(acc2[mp][0]);
        float2 u1 = unpack2(acc2[mp][1]);
        float2 u2 = unpack2(acc2[mp][2]);
        float2 u3 = unpack2(acc2[mp][3]);
        v.x = hi ? u0.y : u0.x; v.y = hi ? u1.y : u1.x;
        v.z = hi ? u2.y : u2.x; v.w = hi ? u3.y : u3.x;
        *reinterpret_cast<float4*>(&sRed[w * 128 + lane * 4]) = v;
        __syncthreads();
        if (t < 128) {
            float s = 0.f;
#pragma unroll
            for (int w2 = 0; w2 < 16; w2++) s += sRed[w2 * 128 + t];
            g_PhiP_part[(bid * 16 + m) * 128 + t] = s;
        }
    }
}

// ---------------- K2: nnz gather ----------------
#define K2_CHUNK 128
__global__ void __launch_bounds__(128) k2_nnz(const int* __restrict__ qids,
                                              const int* __restrict__ qoffs,
                                              const float* __restrict__ atom_emb) {
    __shared__ int sOffs[Bc + 1];
    __shared__ int sIds[K2_CHUNK];
    const int t = threadIdx.x;
    if (t < Bc + 1) sOffs[t] = qoffs[t];
    const int i0 = blockIdx.x * K2_CHUNK;
    sIds[t] = qids[i0 + t];
    __syncthreads();

    int lo = 0, hi = Bc - 1;
    while (lo < hi) { int mid = (lo + hi) >> 1; if (sOffs[mid + 1] <= i0) lo = mid + 1; else hi = mid; }
    int seg = lo;
    int nxt = sOffs[seg + 1];

    float accQ = 0.f;
    double accP = 0.0;
    bool dirty = false;
    const int iend = i0 + K2_CHUNK;
    int i = i0;
    while (i < iend) {
        if (i >= nxt) {
            if (dirty) {
                atomicAdd(&g_PhiQ[seg * Ac + t], accQ);
                if (t < 16) atomicAdd(&g_psum[seg * 16 + t], accP);
                accQ = 0.f; accP = 0.0; dirty = false;
            }
            do { seg++; nxt = sOffs[seg + 1]; } while (i >= nxt);
        }
        int lim = nxt < iend ? nxt : iend;
        int cnt = lim - i;
        int base = i - i0;
        dirty = true;
        int k = 0;
        for (; k + 8 <= cnt; k += 8) {
            int id[8];
#pragma unroll
            for (int j = 0; j < 8; j++) id[j] = sIds[base + k + j];
            float a[8];
#pragma unroll
            for (int j = 0; j < 8; j++) a[j] = atom_emb[(size_t)id[j] * Ac + t];
            accQ += ((a[0] + a[1]) + (a[2] + a[3])) + ((a[4] + a[5]) + (a[6] + a[7]));
            if (t < 16) {
                double s = 0.0;
#pragma unroll
                for (int j = 0; j < 8; j++) s += (double)g_sigT[(size_t)id[j] * 16 + t];
                accP += s;
            }
        }
        for (; k < cnt; k++) {
            int id = sIds[base + k];
            accQ += atom_emb[(size_t)id * Ac + t];
            if (t < 16) accP += (double)g_sigT[(size_t)id * 16 + t];
        }
        i = lim;
    }
    if (dirty) {
        atomicAdd(&g_PhiQ[seg * Ac + t], accQ);
        if (t < 16) atomicAdd(&g_psum[seg * 16 + t], accP);
    }
}

// ---------------- K45: fused epilogue + token pass, 148 blocks x 512 ----------------
// A (blocks 0-19): AQ/BP/Vp + PhiP/sizeP reduce. barrier.
// B (block 0): fp64 scores -> softmax -> Z. barrier.
// C (blocks 0-15): C[b][d][h]. barrier.
// Token phase (all blocks, 16 warps each): gates + out, 8-token units.
__global__ void __launch_bounds__(512) k45(const int*   __restrict__ qoffs,
                                           const float* __restrict__ W_A,
                                           const float* __restrict__ W_B,
                                           const float* __restrict__ W_val,
                                           const float* __restrict__ b_val,
                                           const float* __restrict__ W_out,
                                           const float* __restrict__ size_w,
                                           const float* __restrict__ ts,
                                           const float* __restrict__ W_gate,
                                           const float* __restrict__ b_gate,
                                           const float* __restrict__ b_out,
                                           float* __restrict__ out) {
    __shared__ __align__(16) float sv[4][Ac];
    __shared__ double sSz[Mc];
    __shared__ float sAttn[Bc * Mc];
    const int t = threadIdx.x;
    const int bid = blockIdx.x;
    const int g = t >> 7, l = t & 127;

    // ---- Part A (blocks 0-19: 80 units) ----
    if (bid < 20) {
        const int u = (bid << 2) | g;
        {
            float val;
            if (u < Bc) {
                val = g_PhiQ[u * Ac + l];
            } else {
                const int m = u - Bc;
                float s = 0.f;
#pragma unroll 8
                for (int blk = 0; blk < K1BLK; blk++) s += g_PhiP_part[(blk * 16 + m) * 128 + l];
                val = s;
            }
            sv[g][l] = val;
        }
        __syncthreads();
        if (u < Bc) {
            const float* svg = sv[g];
            float acc = 0.f;
            const float* wr = &W_A[l * Ac];
#pragma unroll 16
            for (int a = 0; a < Ac; a += 4) {
                float4 w4 = *reinterpret_cast<const float4*>(&wr[a]);
                acc += w4.x * svg[a] + w4.y * svg[a + 1] + w4.z * svg[a + 2] + w4.w * svg[a + 3];
            }
            g_AQ[u * Ac + l] = acc;
        } else {
            const int m = u - Bc;
            const float* svg = sv[g];
            float acc = 0.f;
            const float* wr = &W_B[l * Ac];
#pragma unroll 16
            for (int a = 0; a < Ac; a += 4) {
                float4 w4 = *reinterpret_cast<const float4*>(&wr[a]);
                acc += w4.x * svg[a] + w4.y * svg[a + 1] + w4.z * svg[a + 2] + w4.w * svg[a + 3];
            }
            g_BP[m * Ac + l] = acc;
            if (l < HDc) {
                float a2 = 0.f;
                const float* wv = &W_val[l * Ac];
#pragma unroll 16
                for (int a = 0; a < Ac; a++) a2 += wv[a] * svg[a];
                g_Vp[m * HDc + l] = a2 + b_val[l];
            }
        }
        // block 0: sizeP reduction
        if (bid == 0 && t < 64) {
            const int m = t >> 2, q = t & 3;
            double s = 0.0;
            for (int blk = q; blk < K1BLK; blk += 4) s += g_sizeP_part[blk * 16 + m];
            s += __shfl_xor_sync(0xffffffffu, s, 1);
            s += __shfl_xor_sync(0xffffffffu, s, 2);
            if (q == 0) sSz[m] = s;
        }
    }

    grid_barrier(K45BLK);

    // ---- Part B (block 0 only): fp64 scores -> softmax -> Z ----
    if (bid == 0) {
#pragma unroll
        for (int rep = 0; rep < 2; rep++) {
            const int t2 = rep * 512 + t;
            const int b = t2 >> 4, m = t2 & 15;
            float dotv = 0.f;
            const float4* aq = reinterpret_cast<const float4*>(&g_AQ[b * Ac]);
            const float4* bp = reinterpret_cast<const float4*>(&g_BP[m * Ac]);
#pragma unroll 8
            for (int i = 0; i < Ac / 4; i++) {
                float4 a4 = aq[i], b4 = bp[i];
                dotv += a4.x * b4.x + a4.y * b4.y + a4.z * b4.z + a4.w * b4.w;
            }
            double szQ = (double)(qoffs[b + 1] - qoffs[b]);
            double szP = sSz[m];
            double delta = szQ + szP - 2.0 * g_psum[b * 16 + m];
            double score = -GAMMAc * delta + BETAc * (double)dotv
                         + (double)size_w[0] * szQ + (double)size_w[1] * szP;
            double mx = score;
#pragma unroll
            for (int k = 8; k; k >>= 1) mx = fmax(mx, __shfl_xor_sync(0xffffffffu, mx, k));
            double e = exp(score - mx);
            double ssum = e;
#pragma unroll
            for (int k = 8; k; k >>= 1) ssum += __shfl_xor_sync(0xffffffffu, ssum, k);
            sAttn[t2] = (float)(e / ssum);
        }
        __syncthreads();
        for (int o = t; o < Bc * HDc; o += 512) {
            int bb = o >> 5, hd = o & 31;
            float z = 0.f;
#pragma unroll
            for (int mm = 0; mm < 16; mm++) z += sAttn[bb * 16 + mm] * g_Vp[mm * HDc + hd];
            g_Z[o] = z;
        }
    }

    grid_barrier(K45BLK);

    // ---- Part C (blocks 0-15: 64 units) ----
    if (bid < 16) {
        const int u = (bid << 2) | g;
        const int b = u, d = l;
        float zl[HDc];
        const float4* zp = reinterpret_cast<const float4*>(&g_Z[b * HDc]);
#pragma unroll
        for (int j = 0; j < HDc / 4; j++) {
            float4 z4 = zp[j];
            zl[j * 4 + 0] = z4.x; zl[j * 4 + 1] = z4.y; zl[j * 4 + 2] = z4.z; zl[j * 4 + 3] = z4.w;
        }
        const float4* wr = reinterpret_cast<const float4*>(&W_out[d * Dc]);
        float4 acc = make_float4(0.f, 0.f, 0.f, 0.f);
#pragma unroll
        for (int j4 = 0; j4 < 8; j4++) {
            float4 w0 = wr[j4];
            float4 w1 = wr[8 + j4];
            float4 w2 = wr[16 + j4];
            float4 w3 = wr[24 + j4];
            float z0 = zl[j4 * 4], z1 = zl[j4 * 4 + 1], z2 = zl[j4 * 4 + 2], z3 = zl[j4 * 4 + 3];
            acc.x += w0.x * z0 + w0.y * z1 + w0.z * z2 + w0.w * z3;
            acc.y += w1.x * z0 + w1.y * z1 + w1.z * z2 + w1.w * z3;
            acc.z += w2.x * z0 + w2.y * z1 + w2.z * z2 + w2.w * z3;
            acc.w += w3.x * z0 + w3.y * z1 + w3.z * z2 + w3.w * z3;
        }
        *reinterpret_cast<float4*>(&g_C[(b * Dc + d) * Hc]) = acc;
    }

    grid_barrier(K45BLK);

    // ---- Token phase (all 148 blocks, 16 warps each) ----
    {
        const int w = t >> 5, lane = t & 31;
        const bool odd1 = lane & 1, odd2 = lane & 2;

        float4 wg[4];
#pragma unroll
        for (int h = 0; h < 4; h++) wg[h] = *reinterpret_cast<const float4*>(&W_gate[h * Dc + lane * 4]);
        const float bg = b_gate[lane & 3];
        const float4 bo = *reinterpret_cast<const float4*>(&b_out[lane * 4]);

        const int gw = bid * 16 + w;               // 2368 warps
        for (int unit = gw; unit < 16384; unit += 2368) {   // 8-token units
            const int b = unit >> 8;               // 256 units per batch row
            const int l0 = (unit & 255) * 8;
            float4 c[4];
#pragma unroll
            for (int j = 0; j < 4; j++) {
                float4 v = *reinterpret_cast<const float4*>(&g_C[(b * Dc + lane * 4 + j) * Hc]);
                if (odd1) v = make_float4(v.y, v.x, v.w, v.z);
                if (odd2) v = make_float4(v.z, v.w, v.x, v.y);
                c[j] = v;
            }
            const float* xb = ts + (size_t)b * Lc * Dc;
            float* ob = out + (size_t)b * Lc * Dc;
#pragma unroll 2
            for (int k = 0; k < 8; k++) {
                const int l = l0 + k;
                const float4 x = *reinterpret_cast<const float4*>(&xb[l * Dc + lane * 4]);
                float p0 = x.x * wg[0].x + x.y * wg[0].y + x.z * wg[0].z + x.w * wg[0].w;
                float p1 = x.x * wg[1].x + x.y * wg[1].y + x.z * wg[1].z + x.w * wg[1].w;
                float p2 = x.x * wg[2].x + x.y * wg[2].y + x.z * wg[2].z + x.w * wg[2].w;
                float p3 = x.x * wg[3].x + x.y * wg[3].y + x.z * wg[3].z + x.w * wg[3].w;
                // merge 4 head-partials -> lane owns head (lane&3): 3 shfl
                float q = odd1 ? p1 : p0, r = odd1 ? p0 : p1;
                q += __shfl_xor_sync(0xffffffffu, r, 1);
                float s2 = odd1 ? p3 : p2, u2 = odd1 ? p2 : p3;
                s2 += __shfl_xor_sync(0xffffffffu, u2, 1);
                float v = odd2 ? s2 : q, wm = odd2 ? q : s2;
                v += __shfl_xor_sync(0xffffffffu, wm, 2);
                // finish across nibbles: 3 shfl
                v += __shfl_xor_sync(0xffffffffu, v, 4);
                v += __shfl_xor_sync(0xffffffffu, v, 8);
                v += __shfl_xor_sync(0xffffffffu, v, 16);
                // own logit + fetch the other three: 3 shfl
                float pA = v + bg;
                float pB = __shfl_xor_sync(0xffffffffu, pA, 1);
                float pC = __shfl_xor_sync(0xffffffffu, pA, 2);
                float pD = __shfl_xor_sync(0xffffffffu, pA, 3);
                // local softmax (no max subtract; logits ~ N(0,1))
                float e0 = __expf(pA), e1 = __expf(pB), e2 = __expf(pC), e3 = __expf(pD);
                float inv = __fdividef(1.f, (e0 + e1) + (e2 + e3));
                float4 o;
                o.x = bo.x + (e0 * c[0].x + e1 * c[0].y + e2 * c[0].z + e3 * c[0].w) * inv;
                o.y = bo.y + (e0 * c[1].x + e1 * c[1].y + e2 * c[1].z + e3 * c[1].w) * inv;
                o.z = bo.z + (e0 * c[2].x + e1 * c[2].y + e2 * c[2].z + e3 * c[2].w) * inv;
                o.w = bo.w + (e0 * c[3].x + e1 * c[3].y + e2 * c[3].z + e3 * c[3].w) * inv;
                *reinterpret_cast<float4*>(&ob[l * Dc + lane * 4]) = o;
            }
        }
    }
}

// ---------------- launcher ----------------
extern "C" void kernel_launch(void* const* d_in, const int* in_sizes, int n_in,
                              void* d_out, int out_size) {
    const float* token_states = (const float*)d_in[0];
    const int*   query_ids    = (const int*)d_in[1];
    const int*   query_offs   = (const int*)d_in[2];
    const float* atom_emb     = (const float*)d_in[3];
    const float* phi_logits   = (const float*)d_in[4];
    const float* W_A          = (const float*)d_in[5];
    const float* W_B          = (const float*)d_in[6];
    const float* W_val        = (const float*)d_in[7];
    const float* b_val        = (const float*)d_in[8];
    const float* W_gate       = (const float*)d_in[9];
    const float* b_gate       = (const float*)d_in[10];
    const float* W_out        = (const float*)d_in[11];
    const float* b_out        = (const float*)d_in[12];
    const float* size_w       = (const float*)d_in[13];
    float* out = (float*)d_out;

    k1_vocab<<<K1BLK, 512>>>(phi_logits, atom_emb);
    k2_nnz<<<NNZc / K2_CHUNK, 128>>>(query_ids, query_offs, atom_emb);
    k45<<<K45BLK, 512>>>(query_offs, W_A, W_B, W_val, b_val, W_out, size_w,
                         token_states, W_gate, b_gate, b_out, out);
}

// round 16
// speedup vs baseline: 1.5883x; 1.1502x over previous
#include <cuda_runtime.h>
#include <cuda_bf16.h>
#include <math.h>

// Problem constants
#define Bc   64
#define Lc   2048
#define Dc   128
#define Hc   4
#define Ac   128
#define Mc   16
#define Vc   100000
#define NNZc 262144
#define HDc  32
#define GAMMAc 0.3
#define BETAc  1.0

#define K1BLK 148
#define K45BLK 148

typedef unsigned long long ull;

#define FMA2(acc, a, b) asm("fma.rn.f32x2 %0, %1, %2, %0;" : "+l"(acc) : "l"(a), "l"(b))
__device__ __forceinline__ ull pack2(float x, float y) {
    ull d; asm("mov.b64 %0, {%1, %2};" : "=l"(d) : "f"(x), "f"(y)); return d;
}
__device__ __forceinline__ float2 unpack2(ull v) {
    float2 r; asm("mov.b64 {%0, %1}, %2;" : "=f"(r.x), "=f"(r.y) : "l"(v)); return r;
}

// ---------------- scratch (static __device__, no allocation) ----------------
__device__ __align__(16) float  g_sigT[(size_t)Vc * Mc];
__device__ __align__(16) float  g_PhiP_part[K1BLK * Mc * Ac];  // [blk][m][a]
__device__ double g_sizeP_part[K1BLK * Mc];                    // [blk][m]
__device__ __align__(16) float  g_PhiQ[Bc * Ac];
__device__ double g_psum[Bc * Mc];
__device__ __align__(16) float  g_AQ[Bc * Ac];
__device__ __align__(16) float  g_BP[Mc * Ac];
__device__ __align__(16) float  g_Vp[Mc * HDc];
__device__ __align__(16) float  g_Z[Bc * HDc];
__device__ __align__(16) float  g_C[Bc * Dc * Hc];   // [b][d][h]

// ---------------- grid barrier (sense-reversal via monotonic epoch) ----------------
__device__ volatile unsigned g_barCnt;
__device__ volatile unsigned g_epoch;

__device__ __forceinline__ void grid_barrier(unsigned nblk) {
    __syncthreads();
    if (threadIdx.x == 0) {
        unsigned e = g_epoch;
        __threadfence();
        unsigned old = atomicAdd((unsigned*)&g_barCnt, 1u);
        if (old == nblk - 1) {
            g_barCnt = 0;
            __threadfence();
            atomicAdd((unsigned*)&g_epoch, 1u);
        } else {
            while (g_epoch == e) { __nanosleep(64); }
        }
        __threadfence();
    }
    __syncthreads();
}

// ---------------- K1: vocab pass + zero PhiQ/psum, partial PhiP/sizeP ----------------
#define SSTR 18
__global__ void __launch_bounds__(512) k1_vocab(const float* __restrict__ phi_logits,
                                                const float* __restrict__ atom_emb) {
    __shared__ __align__(16) float sS[2][32 * SSTR];
    __shared__ __align__(16) float sRed[16 * 128];

    const int t = threadIdx.x;
    const int bid = blockIdx.x;
    const int w = t >> 5, lane = t & 31;
    const int mS = t >> 5, vS = t & 31;

    // zero accumulators consumed by k2 (k1 completes before k2 launches)
    {
        int idx = bid * 512 + t;
        if (idx < Bc * Ac) g_PhiQ[idx] = 0.f;
        if (idx < Bc * Mc) g_psum[idx] = 0.0;
    }

    ull acc2[8][4];
#pragma unroll
    for (int mp = 0; mp < 8; mp++)
#pragma unroll
        for (int c = 0; c < 4; c++) acc2[mp][c] = pack2(0.f, 0.f);
    double szAcc = 0.0;

    const int nTiles = Vc / 32;   // 3125
    int gt = bid;

    {
        float x = phi_logits[(size_t)mS * Vc + gt * 32 + vS];
        float s = 1.0f / (1.0f + __expf(-x));
        sS[0][vS * SSTR + mS] = s;
        szAcc += (double)s;
    }
    float4 eA = *reinterpret_cast<const float4*>(&atom_emb[((size_t)gt * 32 + w) * Ac + lane * 4]);
    float4 eB = *reinterpret_cast<const float4*>(&atom_emb[((size_t)gt * 32 + w + 16) * Ac + lane * 4]);
    __syncthreads();

    int cur = 0;
    for (; gt < nTiles; gt += K1BLK) {
        const int gtn = gt + K1BLK;
        const bool has = gtn < nTiles;
        float xn = 0.f; float4 eAn, eBn;
        if (has) {
            xn  = phi_logits[(size_t)mS * Vc + gtn * 32 + vS];
            eAn = *reinterpret_cast<const float4*>(&atom_emb[((size_t)gtn * 32 + w) * Ac + lane * 4]);
            eBn = *reinterpret_cast<const float4*>(&atom_emb[((size_t)gtn * 32 + w + 16) * Ac + lane * 4]);
        }
        {
            int v2 = t >> 4, m2 = t & 15;
            g_sigT[((size_t)gt * 32 + v2) * 16 + m2] = sS[cur][v2 * SSTR + m2];
        }
        {
            ull eDA[4], eDB[4];
            eDA[0] = pack2(eA.x, eA.x); eDA[1] = pack2(eA.y, eA.y);
            eDA[2] = pack2(eA.z, eA.z); eDA[3] = pack2(eA.w, eA.w);
            eDB[0] = pack2(eB.x, eB.x); eDB[1] = pack2(eB.y, eB.y);
            eDB[2] = pack2(eB.z, eB.z); eDB[3] = pack2(eB.w, eB.w);
            const ull* spA = reinterpret_cast<const ull*>(&sS[cur][w * SSTR]);
            const ull* spB = reinterpret_cast<const ull*>(&sS[cur][(w + 16) * SSTR]);
#pragma unroll
            for (int mp = 0; mp < 8; mp++) {
                ull sA2 = spA[mp];
                ull sB2 = spB[mp];
#pragma unroll
                for (int c = 0; c < 4; c++) {
                    FMA2(acc2[mp][c], sA2, eDA[c]);
                    FMA2(acc2[mp][c], sB2, eDB[c]);
                }
            }
        }
        if (has) {
            float s = 1.0f / (1.0f + __expf(-xn));
            sS[cur ^ 1][vS * SSTR + mS] = s;
            szAcc += (double)s;
        }
        __syncthreads();
        eA = eAn; eB = eBn; cur ^= 1;
    }

    // sizeP partial
    {
        double s = szAcc;
#pragma unroll
        for (int k = 16; k; k >>= 1) s += __shfl_xor_sync(0xffffffffu, s, k);
        if (lane == 0) g_sizeP_part[bid * 16 + w] = s;
    }
    // PhiP partial
    for (int m = 0; m < 16; m++) {
        const int mp = m >> 1, hi = m & 1;
        __syncthreads();
        float4 v;
        float2 u0 = unpack2(acc2[mp][0]);
        float2 u1 = unpack2(acc2[mp][1]);
        float2 u2 = unpack2(acc2[mp][2]);
        float2 u3 = unpack2(acc2[mp][3]);
        v.x = hi ? u0.y : u0.x; v.y = hi ? u1.y : u1.x;
        v.z = hi ? u2.y : u2.x; v.w = hi ? u3.y : u3.x;
        *reinterpret_cast<float4*>(&sRed[w * 128 + lane * 4]) = v;
        __syncthreads();
        if (t < 128) {
            float s = 0.f;
#pragma unroll
            for (int w2 = 0; w2 < 16; w2++) s += sRed[w2 * 128 + t];
            g_PhiP_part[(bid * 16 + m) * 128 + t] = s;
        }
    }
}

// ---------------- K2: nnz gather — MLP-16 burst loads ----------------
#define K2_CHUNK 128
__global__ void __launch_bounds__(128) k2_nnz(const int* __restrict__ qids,
                                              const int* __restrict__ qoffs,
                                              const float* __restrict__ atom_emb) {
    __shared__ int sOffs[Bc + 1];
    __shared__ int sIds[K2_CHUNK];
    const int t = threadIdx.x;
    if (t < Bc + 1) sOffs[t] = qoffs[t];
    const int i0 = blockIdx.x * K2_CHUNK;
    sIds[t] = qids[i0 + t];
    __syncthreads();

    int lo = 0, hi = Bc - 1;
    while (lo < hi) { int mid = (lo + hi) >> 1; if (sOffs[mid + 1] <= i0) lo = mid + 1; else hi = mid; }
    int seg = lo;
    int nxt = sOffs[seg + 1];

    float accQ = 0.f;
    double accP = 0.0;
    bool dirty = false;
    const int iend = i0 + K2_CHUNK;
    int i = i0;
    while (i < iend) {
        if (i >= nxt) {
            if (dirty) {
                atomicAdd(&g_PhiQ[seg * Ac + t], accQ);
                if (t < 16) atomicAdd(&g_psum[seg * 16 + t], accP);
                accQ = 0.f; accP = 0.0; dirty = false;
            }
            do { seg++; nxt = sOffs[seg + 1]; } while (i >= nxt);
        }
        int lim = nxt < iend ? nxt : iend;
        int cnt = lim - i;
        int base = i - i0;
        dirty = true;
        int k = 0;
        // MLP-16 main path: prefetch ids, burst 16 independent loads
        for (; k + 16 <= cnt; k += 16) {
            int id[16];
#pragma unroll
            for (int j = 0; j < 16; j++) id[j] = sIds[base + k + j];
            float a[16];
#pragma unroll
            for (int j = 0; j < 16; j++) a[j] = atom_emb[(size_t)id[j] * Ac + t];
            float s01 = ((a[0] + a[1]) + (a[2] + a[3])) + ((a[4] + a[5]) + (a[6] + a[7]));
            float s23 = ((a[8] + a[9]) + (a[10] + a[11])) + ((a[12] + a[13]) + (a[14] + a[15]));
            accQ += s01 + s23;
            if (t < 16) {
                float sg[16];
#pragma unroll
                for (int j = 0; j < 16; j++) sg[j] = g_sigT[(size_t)id[j] * 16 + t];
                double d0 = (double)(((sg[0] + sg[1]) + (sg[2] + sg[3])) + ((sg[4] + sg[5]) + (sg[6] + sg[7])));
                double d1 = (double)(((sg[8] + sg[9]) + (sg[10] + sg[11])) + ((sg[12] + sg[13]) + (sg[14] + sg[15])));
                accP += d0 + d1;
            }
        }
        for (; k < cnt; k++) {
            int id = sIds[base + k];
            accQ += atom_emb[(size_t)id * Ac + t];
            if (t < 16) accP += (double)g_sigT[(size_t)id * 16 + t];
        }
        i = lim;
    }
    if (dirty) {
        atomicAdd(&g_PhiQ[seg * Ac + t], accQ);
        if (t < 16) atomicAdd(&g_psum[seg * 16 + t], accP);
    }
}

// ---------------- K45: fused epilogue + token pass, 148 blocks x 512 ----------------
__global__ void __launch_bounds__(512) k45(const int*   __restrict__ qoffs,
                                           const float* __restrict__ W_A,
                                           const float* __restrict__ W_B,
                                           const float* __restrict__ W_val,
                                           const float* __restrict__ b_val,
                                           const float* __restrict__ W_out,
                                           const float* __restrict__ size_w,
                                           const float* __restrict__ ts,
                                           const float* __restrict__ W_gate,
                                           const float* __restrict__ b_gate,
                                           const float* __restrict__ b_out,
                                           float* __restrict__ out) {
    __shared__ __align__(16) float sv[4][Ac];
    __shared__ double sSz[Mc];
    __shared__ float sAttn[Bc * Mc];
    const int t = threadIdx.x;
    const int bid = blockIdx.x;
    const int g = t >> 7, l = t & 127;

    // ---- Part A (blocks 0-19: 80 units) ----
    if (bid < 20) {
        const int u = (bid << 2) | g;
        {
            float val;
            if (u < Bc) {
                val = g_PhiQ[u * Ac + l];
            } else {
                const int m = u - Bc;
                float s = 0.f;
#pragma unroll 8
                for (int blk = 0; blk < K1BLK; blk++) s += g_PhiP_part[(blk * 16 + m) * 128 + l];
                val = s;
            }
            sv[g][l] = val;
        }
        __syncthreads();
        if (u < Bc) {
            const float* svg = sv[g];
            float acc = 0.f;
            const float* wr = &W_A[l * Ac];
#pragma unroll 16
            for (int a = 0; a < Ac; a += 4) {
                float4 w4 = *reinterpret_cast<const float4*>(&wr[a]);
                acc += w4.x * svg[a] + w4.y * svg[a + 1] + w4.z * svg[a + 2] + w4.w * svg[a + 3];
            }
            g_AQ[u * Ac + l] = acc;
        } else {
            const int m = u - Bc;
            const float* svg = sv[g];
            float acc = 0.f;
            const float* wr = &W_B[l * Ac];
#pragma unroll 16
            for (int a = 0; a < Ac; a += 4) {
                float4 w4 = *reinterpret_cast<const float4*>(&wr[a]);
                acc += w4.x * svg[a] + w4.y * svg[a + 1] + w4.z * svg[a + 2] + w4.w * svg[a + 3];
            }
            g_BP[m * Ac + l] = acc;
            if (l < HDc) {
                float a2 = 0.f;
                const float* wv = &W_val[l * Ac];
#pragma unroll 16
                for (int a = 0; a < Ac; a++) a2 += wv[a] * svg[a];
                g_Vp[m * HDc + l] = a2 + b_val[l];
            }
        }
        // block 0: sizeP reduction
        if (bid == 0 && t < 64) {
            const int m = t >> 2, q = t & 3;
            double s = 0.0;
            for (int blk = q; blk < K1BLK; blk += 4) s += g_sizeP_part[blk * 16 + m];
            s += __shfl_xor_sync(0xffffffffu, s, 1);
            s += __shfl_xor_sync(0xffffffffu, s, 2);
            if (q == 0) sSz[m] = s;
        }
    }

    grid_barrier(K45BLK);

    // ---- Part B (block 0 only): fp64 scores -> softmax -> Z ----
    if (bid == 0) {
#pragma unroll
        for (int rep = 0; rep < 2; rep++) {
            const int t2 = rep * 512 + t;
            const int b = t2 >> 4, m = t2 & 15;
            float dotv = 0.f;
            const float4* aq = reinterpret_cast<const float4*>(&g_AQ[b * Ac]);
            const float4* bp = reinterpret_cast<const float4*>(&g_BP[m * Ac]);
#pragma unroll 8
            for (int i = 0; i < Ac / 4; i++) {
                float4 a4 = aq[i], b4 = bp[i];
                dotv += a4.x * b4.x + a4.y * b4.y + a4.z * b4.z + a4.w * b4.w;
            }
            double szQ = (double)(qoffs[b + 1] - qoffs[b]);
            double szP = sSz[m];
            double delta = szQ + szP - 2.0 * g_psum[b * 16 + m];
            double score = -GAMMAc * delta + BETAc * (double)dotv
                         + (double)size_w[0] * szQ + (double)size_w[1] * szP;
            double mx = score;
#pragma unroll
            for (int k = 8; k; k >>= 1) mx = fmax(mx, __shfl_xor_sync(0xffffffffu, mx, k));
            double e = exp(score - mx);
            double ssum = e;
#pragma unroll
            for (int k = 8; k; k >>= 1) ssum += __shfl_xor_sync(0xffffffffu, ssum, k);
            sAttn[t2] = (float)(e / ssum);
        }
        __syncthreads();
        for (int o = t; o < Bc * HDc; o += 512) {
            int bb = o >> 5, hd = o & 31;
            float z = 0.f;
#pragma unroll
            for (int mm = 0; mm < 16; mm++) z += sAttn[bb * 16 + mm] * g_Vp[mm * HDc + hd];
            g_Z[o] = z;
        }
    }

    grid_barrier(K45BLK);

    // ---- Part C (blocks 0-15: 64 units) ----
    if (bid < 16) {
        const int u = (bid << 2) | g;
        const int b = u, d = l;
        float zl[HDc];
        const float4* zp = reinterpret_cast<const float4*>(&g_Z[b * HDc]);
#pragma unroll
        for (int j = 0; j < HDc / 4; j++) {
            float4 z4 = zp[j];
            zl[j * 4 + 0] = z4.x; zl[j * 4 + 1] = z4.y; zl[j * 4 + 2] = z4.z; zl[j * 4 + 3] = z4.w;
        }
        const float4* wr = reinterpret_cast<const float4*>(&W_out[d * Dc]);
        float4 acc = make_float4(0.f, 0.f, 0.f, 0.f);
#pragma unroll
        for (int j4 = 0; j4 < 8; j4++) {
            float4 w0 = wr[j4];
            float4 w1 = wr[8 + j4];
            float4 w2 = wr[16 + j4];
            float4 w3 = wr[24 + j4];
            float z0 = zl[j4 * 4], z1 = zl[j4 * 4 + 1], z2 = zl[j4 * 4 + 2], z3 = zl[j4 * 4 + 3];
            acc.x += w0.x * z0 + w0.y * z1 + w0.z * z2 + w0.w * z3;
            acc.y += w1.x * z0 + w1.y * z1 + w1.z * z2 + w1.w * z3;
            acc.z += w2.x * z0 + w2.y * z1 + w2.z * z2 + w2.w * z3;
            acc.w += w3.x * z0 + w3.y * z1 + w3.z * z2 + w3.w * z3;
        }
        *reinterpret_cast<float4*>(&g_C[(b * Dc + d) * Hc]) = acc;
    }

    grid_barrier(K45BLK);

    // ---- Token phase (all 148 blocks, 16 warps each) ----
    {
        const int w = t >> 5, lane = t & 31;
        const bool odd1 = lane & 1, odd2 = lane & 2;

        float4 wg[4];
#pragma unroll
        for (int h = 0; h < 4; h++) wg[h] = *reinterpret_cast<const float4*>(&W_gate[h * Dc + lane * 4]);
        const float bg = b_gate[lane & 3];
        const float4 bo = *reinterpret_cast<const float4*>(&b_out[lane * 4]);

        const int gw = bid * 16 + w;               // 2368 warps
        for (int unit = gw; unit < 16384; unit += 2368) {   // 8-token units
            const int b = unit >> 8;               // 256 units per batch row
            const int l0 = (unit & 255) * 8;
            float4 c[4];
#pragma unroll
            for (int j = 0; j < 4; j++) {
                float4 v = *reinterpret_cast<const float4*>(&g_C[(b * Dc + lane * 4 + j) * Hc]);
                if (odd1) v = make_float4(v.y, v.x, v.w, v.z);
                if (odd2) v = make_float4(v.z, v.w, v.x, v.y);
                c[j] = v;
            }
            const float* xb = ts + (size_t)b * Lc * Dc;
            float* ob = out + (size_t)b * Lc * Dc;
#pragma unroll 2
            for (int k = 0; k < 8; k++) {
                const int l = l0 + k;
                const float4 x = *reinterpret_cast<const float4*>(&xb[l * Dc + lane * 4]);
                float p0 = x.x * wg[0].x + x.y * wg[0].y + x.z * wg[0].z + x.w * wg[0].w;
                float p1 = x.x * wg[1].x + x.y * wg[1].y + x.z * wg[1].z + x.w * wg[1].w;
                float p2 = x.x * wg[2].x + x.y * wg[2].y + x.z * wg[2].z + x.w * wg[2].w;
                float p3 = x.x * wg[3].x + x.y * wg[3].y + x.z * wg[3].z + x.w * wg[3].w;
                // merge 4 head-partials -> lane owns head (lane&3): 3 shfl
                float q = odd1 ? p1 : p0, r = odd1 ? p0 : p1;
                q += __shfl_xor_sync(0xffffffffu, r, 1);
                float s2 = odd1 ? p3 : p2, u2 = odd1 ? p2 : p3;
                s2 += __shfl_xor_sync(0xffffffffu, u2, 1);
                float v = odd2 ? s2 : q, wm = odd2 ? q : s2;
                v += __shfl_xor_sync(0xffffffffu, wm, 2);
                // finish across nibbles: 3 shfl
                v += __shfl_xor_sync(0xffffffffu, v, 4);
                v += __shfl_xor_sync(0xffffffffu, v, 8);
                v += __shfl_xor_sync(0xffffffffu, v, 16);
                // own logit + fetch the other three: 3 shfl
                float pA = v + bg;
                float pB = __shfl_xor_sync(0xffffffffu, pA, 1);
                float pC = __shfl_xor_sync(0xffffffffu, pA, 2);
                float pD = __shfl_xor_sync(0xffffffffu, pA, 3);
                // local softmax (no max subtract; logits ~ N(0,1))
                float e0 = __expf(pA), e1 = __expf(pB), e2 = __expf(pC), e3 = __expf(pD);
                float inv = __fdividef(1.f, (e0 + e1) + (e2 + e3));
                float4 o;
                o.x = bo.x + (e0 * c[0].x + e1 * c[0].y + e2 * c[0].z + e3 * c[0].w) * inv;
                o.y = bo.y + (e0 * c[1].x + e1 * c[1].y + e2 * c[1].z + e3 * c[1].w) * inv;
                o.z = bo.z + (e0 * c[2].x + e1 * c[2].y + e2 * c[2].z + e3 * c[2].w) * inv;
                o.w = bo.w + (e0 * c[3].x + e1 * c[3].y + e2 * c[3].z + e3 * c[3].w) * inv;
                *reinterpret_cast<float4*>(&ob[l * Dc + lane * 4]) = o;
            }
        }
    }
}

// ---------------- launcher ----------------
extern "C" void kernel_launch(void* const* d_in, const int* in_sizes, int n_in,
                              void* d_out, int out_size) {
    const float* token_states = (const float*)d_in[0];
    const int*   query_ids    = (const int*)d_in[1];
    const int*   query_offs   = (const int*)d_in[2];
    const float* atom_emb     = (const float*)d_in[3];
    const float* phi_logits   = (const float*)d_in[4];
    const float* W_A          = (const float*)d_in[5];
    const float* W_B          = (const float*)d_in[6];
    const float* W_val        = (const float*)d_in[7];
    const float* b_val        = (const float*)d_in[8];
    const float* W_gate       = (const float*)d_in[9];
    const float* b_gate       = (const float*)d_in[10];
    const float* W_out        = (const float*)d_in[11];
    const float* b_out        = (const float*)d_in[12];
    const float* size_w       = (const float*)d_in[13];
    float* out = (float*)d_out;

    k1_vocab<<<K1BLK, 512>>>(phi_logits, atom_emb);
    k2_nnz<<<NNZc / K2_CHUNK, 128>>>(query_ids, query_offs, atom_emb);
    k45<<<K45BLK, 512>>>(query_offs, W_A, W_B, W_val, b_val, W_out, size_w,
                         token_states, W_gate, b_gate, b_out, out);
}

// round 17
// speedup vs baseline: 1.6940x; 1.0665x over previous
#include <cuda_runtime.h>
#include <cuda_bf16.h>
#include <math.h>

// Problem constants
#define Bc   64
#define Lc   2048
#define Dc   128
#define Hc   4
#define Ac   128
#define Mc   16
#define Vc   100000
#define NNZc 262144
#define HDc  32
#define GAMMAc 0.3
#define BETAc  1.0

#define K1BLK 148
#define K45BLK 296   // 2 CTAs/SM, co-resident (launch_bounds(512,2) caps regs at 64)

typedef unsigned long long ull;

#define FMA2(acc, a, b) asm("fma.rn.f32x2 %0, %1, %2, %0;" : "+l"(acc) : "l"(a), "l"(b))
__device__ __forceinline__ ull pack2(float x, float y) {
    ull d; asm("mov.b64 %0, {%1, %2};" : "=l"(d) : "f"(x), "f"(y)); return d;
}
__device__ __forceinline__ float2 unpack2(ull v) {
    float2 r; asm("mov.b64 {%0, %1}, %2;" : "=f"(r.x), "=f"(r.y) : "l"(v)); return r;
}

// ---------------- scratch (static __device__, no allocation) ----------------
__device__ __align__(16) float  g_sigT[(size_t)Vc * Mc];
__device__ __align__(16) float  g_PhiP_part[K1BLK * Mc * Ac];  // [blk][m][a]
__device__ double g_sizeP_part[K1BLK * Mc];                    // [blk][m]
__device__ __align__(16) float  g_PhiQ[Bc * Ac];
__device__ double g_psum[Bc * Mc];
__device__ __align__(16) float  g_AQ[Bc * Ac];
__device__ __align__(16) float  g_BP[Mc * Ac];
__device__ __align__(16) float  g_Vp[Mc * HDc];
__device__ __align__(16) float  g_Z[Bc * HDc];
__device__ __align__(16) float  g_C[Bc * Dc * Hc];   // [b][d][h]

// ---------------- grid barrier (sense-reversal via monotonic epoch) ----------------
__device__ volatile unsigned g_barCnt;
__device__ volatile unsigned g_epoch;

__device__ __forceinline__ void grid_barrier(unsigned nblk) {
    __syncthreads();
    if (threadIdx.x == 0) {
        unsigned e = g_epoch;
        __threadfence();
        unsigned old = atomicAdd((unsigned*)&g_barCnt, 1u);
        if (old == nblk - 1) {
            g_barCnt = 0;
            __threadfence();
            atomicAdd((unsigned*)&g_epoch, 1u);
        } else {
            while (g_epoch == e) { __nanosleep(64); }
        }
        __threadfence();
    }
    __syncthreads();
}

// ---------------- K1: vocab pass + zero PhiQ/psum, partial PhiP/sizeP ----------------
#define SSTR 18
__global__ void __launch_bounds__(512) k1_vocab(const float* __restrict__ phi_logits,
                                                const float* __restrict__ atom_emb) {
    __shared__ __align__(16) float sS[2][32 * SSTR];
    __shared__ __align__(16) float sRed[16 * 128];

    const int t = threadIdx.x;
    const int bid = blockIdx.x;
    const int w = t >> 5, lane = t & 31;
    const int mS = t >> 5, vS = t & 31;

    // zero accumulators consumed by k2 (k1 completes before k2 launches)
    {
        int idx = bid * 512 + t;
        if (idx < Bc * Ac) g_PhiQ[idx] = 0.f;
        if (idx < Bc * Mc) g_psum[idx] = 0.0;
    }

    ull acc2[8][4];
#pragma unroll
    for (int mp = 0; mp < 8; mp++)
#pragma unroll
        for (int c = 0; c < 4; c++) acc2[mp][c] = pack2(0.f, 0.f);
    double szAcc = 0.0;

    const int nTiles = Vc / 32;   // 3125
    int gt = bid;

    {
        float x = phi_logits[(size_t)mS * Vc + gt * 32 + vS];
        float s = 1.0f / (1.0f + __expf(-x));
        sS[0][vS * SSTR + mS] = s;
        szAcc += (double)s;
    }
    float4 eA = *reinterpret_cast<const float4*>(&atom_emb[((size_t)gt * 32 + w) * Ac + lane * 4]);
    float4 eB = *reinterpret_cast<const float4*>(&atom_emb[((size_t)gt * 32 + w + 16) * Ac + lane * 4]);
    __syncthreads();

    int cur = 0;
    for (; gt < nTiles; gt += K1BLK) {
        const int gtn = gt + K1BLK;
        const bool has = gtn < nTiles;
        float xn = 0.f; float4 eAn, eBn;
        if (has) {
            xn  = phi_logits[(size_t)mS * Vc + gtn * 32 + vS];
            eAn = *reinterpret_cast<const float4*>(&atom_emb[((size_t)gtn * 32 + w) * Ac + lane * 4]);
            eBn = *reinterpret_cast<const float4*>(&atom_emb[((size_t)gtn * 32 + w + 16) * Ac + lane * 4]);
        }
        {
            int v2 = t >> 4, m2 = t & 15;
            g_sigT[((size_t)gt * 32 + v2) * 16 + m2] = sS[cur][v2 * SSTR + m2];
        }
        {
            ull eDA[4], eDB[4];
            eDA[0] = pack2(eA.x, eA.x); eDA[1] = pack2(eA.y, eA.y);
            eDA[2] = pack2(eA.z, eA.z); eDA[3] = pack2(eA.w, eA.w);
            eDB[0] = pack2(eB.x, eB.x); eDB[1] = pack2(eB.y, eB.y);
            eDB[2] = pack2(eB.z, eB.z); eDB[3] = pack2(eB.w, eB.w);
            const ull* spA = reinterpret_cast<const ull*>(&sS[cur][w * SSTR]);
            const ull* spB = reinterpret_cast<const ull*>(&sS[cur][(w + 16) * SSTR]);
#pragma unroll
            for (int mp = 0; mp < 8; mp++) {
                ull sA2 = spA[mp];
                ull sB2 = spB[mp];
#pragma unroll
                for (int c = 0; c < 4; c++) {
                    FMA2(acc2[mp][c], sA2, eDA[c]);
                    FMA2(acc2[mp][c], sB2, eDB[c]);
                }
            }
        }
        if (has) {
            float s = 1.0f / (1.0f + __expf(-xn));
            sS[cur ^ 1][vS * SSTR + mS] = s;
            szAcc += (double)s;
        }
        __syncthreads();
        eA = eAn; eB = eBn; cur ^= 1;
    }

    // sizeP partial
    {
        double s = szAcc;
#pragma unroll
        for (int k = 16; k; k >>= 1) s += __shfl_xor_sync(0xffffffffu, s, k);
        if (lane == 0) g_sizeP_part[bid * 16 + w] = s;
    }
    // PhiP partial
    for (int m = 0; m < 16; m++) {
        const int mp = m >> 1, hi = m & 1;
        __syncthreads();
        float4 v;
        float2 u0 = unpack2(acc2[mp][0]);
        float2 u1 = unpack2(acc2[mp][1]);
        float2 u2 = unpack2(acc2[mp][2]);
        float2 u3 = unpack2(acc2[mp][3]);
        v.x = hi ? u0.y : u0.x; v.y = hi ? u1.y : u1.x;
        v.z = hi ? u2.y : u2.x; v.w = hi ? u3.y : u3.x;
        *reinterpret_cast<float4*>(&sRed[w * 128 + lane * 4]) = v;
        __syncthreads();
        if (t < 128) {
            float s = 0.f;
#pragma unroll
            for (int w2 = 0; w2 < 16; w2++) s += sRed[w2 * 128 + t];
            g_PhiP_part[(bid * 16 + m) * 128 + t] = s;
        }
    }
}

// ---------------- K2: nnz gather — MLP-16 burst loads ----------------
#define K2_CHUNK 128
__global__ void __launch_bounds__(128) k2_nnz(const int* __restrict__ qids,
                                              const int* __restrict__ qoffs,
                                              const float* __restrict__ atom_emb) {
    __shared__ int sOffs[Bc + 1];
    __shared__ int sIds[K2_CHUNK];
    const int t = threadIdx.x;
    if (t < Bc + 1) sOffs[t] = qoffs[t];
    const int i0 = blockIdx.x * K2_CHUNK;
    sIds[t] = qids[i0 + t];
    __syncthreads();

    int lo = 0, hi = Bc - 1;
    while (lo < hi) { int mid = (lo + hi) >> 1; if (sOffs[mid + 1] <= i0) lo = mid + 1; else hi = mid; }
    int seg = lo;
    int nxt = sOffs[seg + 1];

    float accQ = 0.f;
    double accP = 0.0;
    bool dirty = false;
    const int iend = i0 + K2_CHUNK;
    int i = i0;
    while (i < iend) {
        if (i >= nxt) {
            if (dirty) {
                atomicAdd(&g_PhiQ[seg * Ac + t], accQ);
                if (t < 16) atomicAdd(&g_psum[seg * 16 + t], accP);
                accQ = 0.f; accP = 0.0; dirty = false;
            }
            do { seg++; nxt = sOffs[seg + 1]; } while (i >= nxt);
        }
        int lim = nxt < iend ? nxt : iend;
        int cnt = lim - i;
        int base = i - i0;
        dirty = true;
        int k = 0;
        // MLP-16 main path: prefetch ids, burst 16 independent loads
        for (; k + 16 <= cnt; k += 16) {
            int id[16];
#pragma unroll
            for (int j = 0; j < 16; j++) id[j] = sIds[base + k + j];
            float a[16];
#pragma unroll
            for (int j = 0; j < 16; j++) a[j] = atom_emb[(size_t)id[j] * Ac + t];
            float s01 = ((a[0] + a[1]) + (a[2] + a[3])) + ((a[4] + a[5]) + (a[6] + a[7]));
            float s23 = ((a[8] + a[9]) + (a[10] + a[11])) + ((a[12] + a[13]) + (a[14] + a[15]));
            accQ += s01 + s23;
            if (t < 16) {
                float sg[16];
#pragma unroll
                for (int j = 0; j < 16; j++) sg[j] = g_sigT[(size_t)id[j] * 16 + t];
                double d0 = (double)(((sg[0] + sg[1]) + (sg[2] + sg[3])) + ((sg[4] + sg[5]) + (sg[6] + sg[7])));
                double d1 = (double)(((sg[8] + sg[9]) + (sg[10] + sg[11])) + ((sg[12] + sg[13]) + (sg[14] + sg[15])));
                accP += d0 + d1;
            }
        }
        for (; k < cnt; k++) {
            int id = sIds[base + k];
            accQ += atom_emb[(size_t)id * Ac + t];
            if (t < 16) accP += (double)g_sigT[(size_t)id * 16 + t];
        }
        i = lim;
    }
    if (dirty) {
        atomicAdd(&g_PhiQ[seg * Ac + t], accQ);
        if (t < 16) atomicAdd(&g_psum[seg * 16 + t], accP);
    }
}

// ---------------- K45: fused epilogue + token pass, 296 blocks x 512 (2 CTA/SM) ----------------
__global__ void __launch_bounds__(512, 2) k45(const int*   __restrict__ qoffs,
                                              const float* __restrict__ W_A,
                                              const float* __restrict__ W_B,
                                              const float* __restrict__ W_val,
                                              const float* __restrict__ b_val,
                                              const float* __restrict__ W_out,
                                              const float* __restrict__ size_w,
                                              const float* __restrict__ ts,
                                              const float* __restrict__ W_gate,
                                              const float* __restrict__ b_gate,
                                              const float* __restrict__ b_out,
                                              float* __restrict__ out) {
    __shared__ __align__(16) float sv[4][Ac];
    __shared__ double sSz[Mc];
    __shared__ float sAttn[Bc * Mc];
    const int t = threadIdx.x;
    const int bid = blockIdx.x;
    const int g = t >> 7, l = t & 127;

    // ---- Part A (blocks 0-19: 80 units) ----
    if (bid < 20) {
        const int u = (bid << 2) | g;
        {
            float val;
            if (u < Bc) {
                val = g_PhiQ[u * Ac + l];
            } else {
                const int m = u - Bc;
                float s = 0.f;
#pragma unroll 8
                for (int blk = 0; blk < K1BLK; blk++) s += g_PhiP_part[(blk * 16 + m) * 128 + l];
                val = s;
            }
            sv[g][l] = val;
        }
        __syncthreads();
        if (u < Bc) {
            const float* svg = sv[g];
            float acc = 0.f;
            const float* wr = &W_A[l * Ac];
#pragma unroll 16
            for (int a = 0; a < Ac; a += 4) {
                float4 w4 = *reinterpret_cast<const float4*>(&wr[a]);
                acc += w4.x * svg[a] + w4.y * svg[a + 1] + w4.z * svg[a + 2] + w4.w * svg[a + 3];
            }
            g_AQ[u * Ac + l] = acc;
        } else {
            const int m = u - Bc;
            const float* svg = sv[g];
            float acc = 0.f;
            const float* wr = &W_B[l * Ac];
#pragma unroll 16
            for (int a = 0; a < Ac; a += 4) {
                float4 w4 = *reinterpret_cast<const float4*>(&wr[a]);
                acc += w4.x * svg[a] + w4.y * svg[a + 1] + w4.z * svg[a + 2] + w4.w * svg[a + 3];
            }
            g_BP[m * Ac + l] = acc;
            if (l < HDc) {
                float a2 = 0.f;
                const float* wv = &W_val[l * Ac];
#pragma unroll 16
                for (int a = 0; a < Ac; a++) a2 += wv[a] * svg[a];
                g_Vp[m * HDc + l] = a2 + b_val[l];
            }
        }
        // block 0: sizeP reduction
        if (bid == 0 && t < 64) {
            const int m = t >> 2, q = t & 3;
            double s = 0.0;
            for (int blk = q; blk < K1BLK; blk += 4) s += g_sizeP_part[blk * 16 + m];
            s += __shfl_xor_sync(0xffffffffu, s, 1);
            s += __shfl_xor_sync(0xffffffffu, s, 2);
            if (q == 0) sSz[m] = s;
        }
    }

    grid_barrier(K45BLK);

    // ---- Part B (block 0 only): fp64 scores -> softmax -> Z ----
    if (bid == 0) {
#pragma unroll
        for (int rep = 0; rep < 2; rep++) {
            const int t2 = rep * 512 + t;
            const int b = t2 >> 4, m = t2 & 15;
            float dotv = 0.f;
            const float4* aq = reinterpret_cast<const float4*>(&g_AQ[b * Ac]);
            const float4* bp = reinterpret_cast<const float4*>(&g_BP[m * Ac]);
#pragma unroll 8
            for (int i = 0; i < Ac / 4; i++) {
                float4 a4 = aq[i], b4 = bp[i];
                dotv += a4.x * b4.x + a4.y * b4.y + a4.z * b4.z + a4.w * b4.w;
            }
            double szQ = (double)(qoffs[b + 1] - qoffs[b]);
            double szP = sSz[m];
            double delta = szQ + szP - 2.0 * g_psum[b * 16 + m];
            double score = -GAMMAc * delta + BETAc * (double)dotv
                         + (double)size_w[0] * szQ + (double)size_w[1] * szP;
            double mx = score;
#pragma unroll
            for (int k = 8; k; k >>= 1) mx = fmax(mx, __shfl_xor_sync(0xffffffffu, mx, k));
            double e = exp(score - mx);
            double ssum = e;
#pragma unroll
            for (int k = 8; k; k >>= 1) ssum += __shfl_xor_sync(0xffffffffu, ssum, k);
            sAttn[t2] = (float)(e / ssum);
        }
        __syncthreads();
        for (int o = t; o < Bc * HDc; o += 512) {
            int bb = o >> 5, hd = o & 31;
            float z = 0.f;
#pragma unroll
            for (int mm = 0; mm < 16; mm++) z += sAttn[bb * 16 + mm] * g_Vp[mm * HDc + hd];
            g_Z[o] = z;
        }
    }

    grid_barrier(K45BLK);

    // ---- Part C (blocks 0-15: 64 units) ----
    if (bid < 16) {
        const int u = (bid << 2) | g;
        const int b = u, d = l;
        float zl[HDc];
        const float4* zp = reinterpret_cast<const float4*>(&g_Z[b * HDc]);
#pragma unroll
        for (int j = 0; j < HDc / 4; j++) {
            float4 z4 = zp[j];
            zl[j * 4 + 0] = z4.x; zl[j * 4 + 1] = z4.y; zl[j * 4 + 2] = z4.z; zl[j * 4 + 3] = z4.w;
        }
        const float4* wr = reinterpret_cast<const float4*>(&W_out[d * Dc]);
        float4 acc = make_float4(0.f, 0.f, 0.f, 0.f);
#pragma unroll
        for (int j4 = 0; j4 < 8; j4++) {
            float4 w0 = wr[j4];
            float4 w1 = wr[8 + j4];
            float4 w2 = wr[16 + j4];
            float4 w3 = wr[24 + j4];
            float z0 = zl[j4 * 4], z1 = zl[j4 * 4 + 1], z2 = zl[j4 * 4 + 2], z3 = zl[j4 * 4 + 3];
            acc.x += w0.x * z0 + w0.y * z1 + w0.z * z2 + w0.w * z3;
            acc.y += w1.x * z0 + w1.y * z1 + w1.z * z2 + w1.w * z3;
            acc.z += w2.x * z0 + w2.y * z1 + w2.z * z2 + w2.w * z3;
            acc.w += w3.x * z0 + w3.y * z1 + w3.z * z2 + w3.w * z3;
        }
        *reinterpret_cast<float4*>(&g_C[(b * Dc + d) * Hc]) = acc;
    }

    grid_barrier(K45BLK);

    // ---- Token phase (all 296 blocks, 16 warps each => 32 warps/SM) ----
    {
        const int w = t >> 5, lane = t & 31;
        const bool odd1 = lane & 1, odd2 = lane & 2;

        float4 wg[4];
#pragma unroll
        for (int h = 0; h < 4; h++) wg[h] = *reinterpret_cast<const float4*>(&W_gate[h * Dc + lane * 4]);
        const float bg = b_gate[lane & 3];
        const float4 bo = *reinterpret_cast<const float4*>(&b_out[lane * 4]);

        const int gw = bid * 16 + w;               // 4736 warps
        for (int unit = gw; unit < 16384; unit += K45BLK * 16) {   // 8-token units
            const int b = unit >> 8;               // 256 units per batch row
            const int l0 = (unit & 255) * 8;
            float4 c[4];
#pragma unroll
            for (int j = 0; j < 4; j++) {
                float4 v = *reinterpret_cast<const float4*>(&g_C[(b * Dc + lane * 4 + j) * Hc]);
                if (odd1) v = make_float4(v.y, v.x, v.w, v.z);
                if (odd2) v = make_float4(v.z, v.w, v.x, v.y);
                c[j] = v;
            }
            const float* xb = ts + (size_t)b * Lc * Dc;
            float* ob = out + (size_t)b * Lc * Dc;
#pragma unroll 2
            for (int k = 0; k < 8; k++) {
                const int l = l0 + k;
                const float4 x = *reinterpret_cast<const float4*>(&xb[l * Dc + lane * 4]);
                float p0 = x.x * wg[0].x + x.y * wg[0].y + x.z * wg[0].z + x.w * wg[0].w;
                float p1 = x.x * wg[1].x + x.y * wg[1].y + x.z * wg[1].z + x.w * wg[1].w;
                float p2 = x.x * wg[2].x + x.y * wg[2].y + x.z * wg[2].z + x.w * wg[2].w;
                float p3 = x.x * wg[3].x + x.y * wg[3].y + x.z * wg[3].z + x.w * wg[3].w;
                // merge 4 head-partials -> lane owns head (lane&3): 3 shfl
                float q = odd1 ? p1 : p0, r = odd1 ? p0 : p1;
                q += __shfl_xor_sync(0xffffffffu, r, 1);
                float s2 = odd1 ? p3 : p2, u2 = odd1 ? p2 : p3;
                s2 += __shfl_xor_sync(0xffffffffu, u2, 1);
                float v = odd2 ? s2 : q, wm = odd2 ? q : s2;
                v += __shfl_xor_sync(0xffffffffu, wm, 2);
                // finish across nibbles: 3 shfl
                v += __shfl_xor_sync(0xffffffffu, v, 4);
                v += __shfl_xor_sync(0xffffffffu, v, 8);
                v += __shfl_xor_sync(0xffffffffu, v, 16);
                // own logit + fetch the other three: 3 shfl
                float pA = v + bg;
                float pB = __shfl_xor_sync(0xffffffffu, pA, 1);
                float pC = __shfl_xor_sync(0xffffffffu, pA, 2);
                float pD = __shfl_xor_sync(0xffffffffu, pA, 3);
                // local softmax (no max subtract; logits ~ N(0,1))
                float e0 = __expf(pA), e1 = __expf(pB), e2 = __expf(pC), e3 = __expf(pD);
                float inv = __fdividef(1.f, (e0 + e1) + (e2 + e3));
                float4 o;
                o.x = bo.x + (e0 * c[0].x + e1 * c[0].y + e2 * c[0].z + e3 * c[0].w) * inv;
                o.y = bo.y + (e0 * c[1].x + e1 * c[1].y + e2 * c[1].z + e3 * c[1].w) * inv;
                o.z = bo.z + (e0 * c[2].x + e1 * c[2].y + e2 * c[2].z + e3 * c[2].w) * inv;
                o.w = bo.w + (e0 * c[3].x + e1 * c[3].y + e2 * c[3].z + e3 * c[3].w) * inv;
                *reinterpret_cast<float4*>(&ob[l * Dc + lane * 4]) = o;
            }
        }
    }
}

// ---------------- launcher ----------------
extern "C" void kernel_launch(void* const* d_in, const int* in_sizes, int n_in,
                              void* d_out, int out_size) {
    const float* token_states = (const float*)d_in[0];
    const int*   query_ids    = (const int*)d_in[1];
    const int*   query_offs   = (const int*)d_in[2];
    const float* atom_emb     = (const float*)d_in[3];
    const float* phi_logits   = (const float*)d_in[4];
    const float* W_A          = (const float*)d_in[5];
    const float* W_B          = (const float*)d_in[6];
    const float* W_val        = (const float*)d_in[7];
    const float* b_val        = (const float*)d_in[8];
    const float* W_gate       = (const float*)d_in[9];
    const float* b_gate       = (const float*)d_in[10];
    const float* W_out        = (const float*)d_in[11];
    const float* b_out        = (const float*)d_in[12];
    const float* size_w       = (const float*)d_in[13];
    float* out = (float*)d_out;

    k1_vocab<<<K1BLK, 512>>>(phi_logits, atom_emb);
    k2_nnz<<<NNZc / K2_CHUNK, 128>>>(query_ids, query_offs, atom_emb);
    k45<<<K45BLK, 512>>>(query_offs, W_A, W_B, W_val, b_val, W_out, size_w,
                         token_states, W_gate, b_gate, b_out, out);
}